// round 1
// baseline (speedup 1.0000x reference)
#include <cuda_runtime.h>
#include <cstdint>

#define Bb   8
#define Cc   256
#define CRr  128
#define Tt   16
#define HWW  784
#define PXB  (Tt * HWW)        // 12544 pixels per (b, channel) slab
#define KTOP 196
#define NN   (Bb * CRr)        // 1024 attention rows

// ---------------- scratch (device globals; no allocation allowed) ----------------
__device__ float g_Q[NN * PXB];        // [n][t][hw]
__device__ float g_K[NN * PXB];
__device__ float g_V[NN * PXB];
__device__ float g_Qtk[NN * Tt * KTOP];
__device__ float g_Ktk[NN * Tt * KTOP];
__device__ float g_Y[NN * PXB];

// ---------------- f32x2 helpers ----------------
__device__ __forceinline__ void fma2(unsigned long long& c, unsigned long long a,
                                     unsigned long long b) {
    asm("fma.rn.f32x2 %0, %1, %2, %0;" : "+l"(c) : "l"(a), "l"(b));
}
__device__ __forceinline__ unsigned long long pk2(float lo, float hi) {
    unsigned long long r;
    asm("mov.b64 %0, {%1, %2};" : "=l"(r) : "f"(lo), "f"(hi));
    return r;
}
__device__ __forceinline__ void upk2(unsigned long long v, float& lo, float& hi) {
    asm("mov.b64 {%0, %1}, %2;" : "=f"(lo), "=f"(hi) : "l"(v));
}

// =====================================================================
// Kernel 1: QKV projection. out[384, px] = W[384,256] @ x[256, px] + bias
// grid (98 px-tiles of 128, 6 out-chunks of 64, 8 batches), 256 threads.
// Per-thread: 8 outs x 4 px, f32x2-packed over px pairs.
// =====================================================================
__global__ __launch_bounds__(256) void qkv_kernel(
    const float* __restrict__ x,
    const float* __restrict__ Wq, const float* __restrict__ bq,
    const float* __restrict__ Wk, const float* __restrict__ bk,
    const float* __restrict__ Wv, const float* __restrict__ bv)
{
    const int pxt = blockIdx.x;            // 0..97
    const int oc  = blockIdx.y;            // 0..5
    const int b   = blockIdx.z;            // 0..7
    const int tid = threadIdx.x;
    const int lane = tid & 31;
    const int r    = tid >> 5;             // 0..7 : out-row group

    const float* W; const float* bias; float* dst; int chbase;
    const int och = oc * 64;
    if (och < 128)      { W = Wq; bias = bq; dst = g_Q; chbase = och; }
    else if (och < 256) { W = Wk; bias = bk; dst = g_K; chbase = och - 128; }
    else                { W = Wv; bias = bv; dst = g_V; chbase = och - 256; }

    __shared__ __align__(16) float Xs[32][128];
    __shared__ unsigned long long Wd[32][64];   // duplicated {w,w} pairs

    const float* xb = x + (size_t)b * Cc * PXB + pxt * 128;

    unsigned long long acc[8][2];
    #pragma unroll
    for (int o = 0; o < 8; o++) { acc[o][0] = 0ULL; acc[o][1] = 0ULL; }

    for (int kt = 0; kt < 256; kt += 32) {
        // X tile: 32 channels x 128 px = 1024 float4 / 256 thr = 4 each
        #pragma unroll
        for (int i = 0; i < 4; i++) {
            int idx = tid + i * 256;
            int row = idx >> 5, col = idx & 31;
            float4 v = *(const float4*)(xb + (size_t)(kt + row) * PXB + col * 4);
            *(float4*)(&Xs[row][col * 4]) = v;
        }
        // W tile: 64 outs x 32 k, store duplicated [k][o]
        #pragma unroll
        for (int i = 0; i < 2; i++) {
            int idx = tid + i * 256;           // 0..511
            int o = idx >> 3, c4 = idx & 7;
            float4 v = *(const float4*)(W + (size_t)(chbase + o) * 256 + kt + c4 * 4);
            Wd[c4 * 4 + 0][o] = pk2(v.x, v.x);
            Wd[c4 * 4 + 1][o] = pk2(v.y, v.y);
            Wd[c4 * 4 + 2][o] = pk2(v.z, v.z);
            Wd[c4 * 4 + 3][o] = pk2(v.w, v.w);
        }
        __syncthreads();
        #pragma unroll 4
        for (int kk = 0; kk < 32; kk++) {
            const unsigned long long* xp =
                (const unsigned long long*)(&Xs[kk][lane * 4]);
            unsigned long long x01 = xp[0];
            unsigned long long x23 = xp[1];
            #pragma unroll
            for (int o = 0; o < 8; o++) {
                unsigned long long w2 = Wd[kk][r * 8 + o];
                fma2(acc[o][0], w2, x01);
                fma2(acc[o][1], w2, x23);
            }
        }
        __syncthreads();
    }

    #pragma unroll
    for (int o = 0; o < 8; o++) {
        int ch = chbase + r * 8 + o;
        float bv_ = bias[ch];
        float4 outv;
        upk2(acc[o][0], outv.x, outv.y);
        upk2(acc[o][1], outv.z, outv.w);
        outv.x += bv_; outv.y += bv_; outv.z += bv_; outv.w += bv_;
        *(float4*)(dst + (size_t)(b * CRr + ch) * PXB + pxt * 128 + lane * 4) = outv;
    }
}

// =====================================================================
// Kernel 2: top-196 sorted descending per (n,t) row of Q and K.
// One block (256 thr) per row; smem bitonic sort of 1024 (pad -inf).
// grid = 2 * 1024 * 16 = 32768
// =====================================================================
__global__ __launch_bounds__(256) void topk_kernel()
{
    __shared__ float s[1024];
    const int row = blockIdx.x;
    const int rl  = row & 16383;
    const float* src; float* dst;
    if (row < 16384) { src = g_Q; dst = g_Qtk; }
    else             { src = g_K; dst = g_Ktk; }
    const float* p = src + (size_t)rl * HWW;

    for (int i = threadIdx.x; i < 1024; i += 256)
        s[i] = (i < HWW) ? p[i] : -__int_as_float(0x7f800000);
    __syncthreads();

    for (int k = 2; k <= 1024; k <<= 1) {
        for (int j = k >> 1; j > 0; j >>= 1) {
            #pragma unroll
            for (int u = 0; u < 4; u++) {
                int i = threadIdx.x + u * 256;
                int ixj = i ^ j;
                if (ixj > i) {
                    float a = s[i], c = s[ixj];
                    bool sw = ((i & k) == 0) ? (a < c) : (a > c);
                    if (sw) { s[i] = c; s[ixj] = a; }
                }
            }
            __syncthreads();
        }
    }
    float* q = dst + (size_t)rl * KTOP;
    if (threadIdx.x < KTOP) q[threadIdx.x] = s[threadIdx.x];
}

// =====================================================================
// Kernel 3: per-n attention: corr = Qtk@Ktk^T (16x16), softmax, Y = attn@V
// grid = 1024, 256 threads.
// =====================================================================
__global__ __launch_bounds__(256) void attn_kernel()
{
    __shared__ float Qs[Tt * KTOP];
    __shared__ float Ks[Tt * KTOP];
    __shared__ float A[Tt * Tt];
    const int n   = blockIdx.x;
    const int tid = threadIdx.x;

    const float* qp = g_Qtk + (size_t)n * Tt * KTOP;
    const float* kp = g_Ktk + (size_t)n * Tt * KTOP;
    for (int i = tid; i < Tt * KTOP; i += 256) { Qs[i] = qp[i]; Ks[i] = kp[i]; }
    __syncthreads();

    {   // corr: one (t,s) per thread
        const int t = tid >> 4, s2 = tid & 15;
        float acc = 0.f;
        #pragma unroll 4
        for (int k = 0; k < KTOP; k++)
            acc += Qs[t * KTOP + k] * Ks[s2 * KTOP + k];
        A[t * 16 + s2] = acc;
    }
    __syncthreads();

    if (tid < 16) {   // softmax row tid
        float m = -1e30f;
        #pragma unroll
        for (int s2 = 0; s2 < 16; s2++) m = fmaxf(m, A[tid * 16 + s2]);
        float e[16], sum = 0.f;
        #pragma unroll
        for (int s2 = 0; s2 < 16; s2++) {
            e[s2] = __expf(A[tid * 16 + s2] - m);
            sum += e[s2];
        }
        float inv = 1.0f / sum;
        #pragma unroll
        for (int s2 = 0; s2 < 16; s2++) A[tid * 16 + s2] = e[s2] * inv;
    }
    __syncthreads();

    const float* vp = g_V + (size_t)n * PXB;
    float*       yp = g_Y + (size_t)n * PXB;
    for (int p = tid; p < HWW; p += 256) {
        float v[16];
        #pragma unroll
        for (int s2 = 0; s2 < 16; s2++) v[s2] = vp[s2 * HWW + p];
        #pragma unroll
        for (int t = 0; t < 16; t++) {
            float acc = 0.f;
            #pragma unroll
            for (int s2 = 0; s2 < 16; s2++) acc += A[t * 16 + s2] * v[s2];
            yp[t * HWW + p] = acc;
        }
    }
}

// =====================================================================
// Kernel 4: reconstruction: out = BN(Wr @ Y + br) + x
// grid (98, 4, 8), 256 threads. Same GEMM micro-structure as kernel 1.
// =====================================================================
__global__ __launch_bounds__(256) void recon_kernel(
    const float* __restrict__ x,
    const float* __restrict__ Wr, const float* __restrict__ br,
    const float* __restrict__ gamma, const float* __restrict__ beta,
    const float* __restrict__ bn_mean, const float* __restrict__ bn_var,
    float* __restrict__ out)
{
    const int pxt = blockIdx.x;
    const int oc  = blockIdx.y;            // 0..3 (chunks of 64 of 256)
    const int b   = blockIdx.z;
    const int tid = threadIdx.x;
    const int lane = tid & 31;
    const int r    = tid >> 5;
    const int och  = oc * 64;

    __shared__ __align__(16) float Ys[32][128];
    __shared__ unsigned long long Wd[32][64];

    const float* yb = g_Y + (size_t)b * CRr * PXB + pxt * 128;

    unsigned long long acc[8][2];
    #pragma unroll
    for (int o = 0; o < 8; o++) { acc[o][0] = 0ULL; acc[o][1] = 0ULL; }

    for (int kt = 0; kt < 128; kt += 32) {
        #pragma unroll
        for (int i = 0; i < 4; i++) {
            int idx = tid + i * 256;
            int row = idx >> 5, col = idx & 31;
            float4 v = *(const float4*)(yb + (size_t)(kt + row) * PXB + col * 4);
            *(float4*)(&Ys[row][col * 4]) = v;
        }
        #pragma unroll
        for (int i = 0; i < 2; i++) {
            int idx = tid + i * 256;
            int o = idx >> 3, c4 = idx & 7;
            float4 v = *(const float4*)(Wr + (size_t)(och + o) * CRr + kt + c4 * 4);
            Wd[c4 * 4 + 0][o] = pk2(v.x, v.x);
            Wd[c4 * 4 + 1][o] = pk2(v.y, v.y);
            Wd[c4 * 4 + 2][o] = pk2(v.z, v.z);
            Wd[c4 * 4 + 3][o] = pk2(v.w, v.w);
        }
        __syncthreads();
        #pragma unroll 4
        for (int kk = 0; kk < 32; kk++) {
            const unsigned long long* yp =
                (const unsigned long long*)(&Ys[kk][lane * 4]);
            unsigned long long y01 = yp[0];
            unsigned long long y23 = yp[1];
            #pragma unroll
            for (int o = 0; o < 8; o++) {
                unsigned long long w2 = Wd[kk][r * 8 + o];
                fma2(acc[o][0], w2, y01);
                fma2(acc[o][1], w2, y23);
            }
        }
        __syncthreads();
    }

    #pragma unroll
    for (int o = 0; o < 8; o++) {
        int ch = och + r * 8 + o;
        float sc = gamma[ch] * rsqrtf(bn_var[ch] + 1e-5f);
        float c0 = sc * br[ch] + beta[ch] - bn_mean[ch] * sc;
        size_t idx = (size_t)(b * Cc + ch) * PXB + pxt * 128 + lane * 4;
        float4 xv = *(const float4*)(x + idx);
        float y0, y1, y2, y3;
        upk2(acc[o][0], y0, y1);
        upk2(acc[o][1], y2, y3);
        float4 ov;
        ov.x = sc * y0 + c0 + xv.x;
        ov.y = sc * y1 + c0 + xv.y;
        ov.z = sc * y2 + c0 + xv.z;
        ov.w = sc * y3 + c0 + xv.w;
        *(float4*)(out + idx) = ov;
    }
}

// =====================================================================
extern "C" void kernel_launch(void* const* d_in, const int* in_sizes, int n_in,
                              void* d_out, int out_size)
{
    const float* x       = (const float*)d_in[0];
    const float* Wq      = (const float*)d_in[1];
    const float* bq      = (const float*)d_in[2];
    const float* Wk      = (const float*)d_in[3];
    const float* bk      = (const float*)d_in[4];
    const float* Wv      = (const float*)d_in[5];
    const float* bv      = (const float*)d_in[6];
    const float* Wr      = (const float*)d_in[7];
    const float* br      = (const float*)d_in[8];
    const float* gamma   = (const float*)d_in[9];
    const float* beta    = (const float*)d_in[10];
    const float* bn_mean = (const float*)d_in[11];
    const float* bn_var  = (const float*)d_in[12];
    float* out = (float*)d_out;

    qkv_kernel<<<dim3(98, 6, Bb), 256>>>(x, Wq, bq, Wk, bk, Wv, bv);
    topk_kernel<<<2 * NN * Tt, 256>>>();
    attn_kernel<<<NN, 256>>>();
    recon_kernel<<<dim3(98, 4, Bb), 256>>>(x, Wr, br, gamma, beta,
                                           bn_mean, bn_var, out);
}

// round 4
// speedup vs baseline: 1.7409x; 1.7409x over previous
#include <cuda_runtime.h>
#include <cstdint>

#define Bb   8
#define Cc   256
#define CRr  128
#define Tt   16
#define HWW  784
#define PXB  (Tt * HWW)        // 12544 pixels per (b, channel) slab
#define KTOP 196
#define NN   (Bb * CRr)        // 1024 attention rows

// ---------------- scratch (device globals; no allocation allowed) ----------------
__device__ float g_Q[NN * PXB];        // [n][t][hw]
__device__ float g_K[NN * PXB];
__device__ float g_V[NN * PXB];
__device__ float g_Qtk[NN * Tt * KTOP];
__device__ float g_Ktk[NN * Tt * KTOP];
__device__ float g_Y[NN * PXB];

// ---------------- f32x2 helpers ----------------
__device__ __forceinline__ void fma2(unsigned long long& c, unsigned long long a,
                                     unsigned long long b) {
    asm("fma.rn.f32x2 %0, %1, %2, %0;" : "+l"(c) : "l"(a), "l"(b));
}
__device__ __forceinline__ unsigned long long pk2(float lo, float hi) {
    unsigned long long r;
    asm("mov.b64 %0, {%1, %2};" : "=l"(r) : "f"(lo), "f"(hi));
    return r;
}
__device__ __forceinline__ void upk2(unsigned long long v, float& lo, float& hi) {
    asm("mov.b64 {%0, %1}, %2;" : "=f"(lo), "=f"(hi) : "l"(v));
}

// =====================================================================
// Kernel 1: QKV projection. out[384, px] = W[384,256] @ x[256, px] + bias
// grid (98 px-tiles of 128, 6 out-chunks of 64, 8 batches), 256 threads.
// Per-thread: 8 outs x 4 px; all smem traffic via LDS.128.
// =====================================================================
__global__ __launch_bounds__(256) void qkv_kernel(
    const float* __restrict__ x,
    const float* __restrict__ Wq, const float* __restrict__ bq,
    const float* __restrict__ Wk, const float* __restrict__ bk,
    const float* __restrict__ Wv, const float* __restrict__ bv)
{
    const int pxt = blockIdx.x;            // 0..97
    const int oc  = blockIdx.y;            // 0..5
    const int b   = blockIdx.z;            // 0..7
    const int tid = threadIdx.x;
    const int lane = tid & 31;
    const int r    = tid >> 5;             // 0..7 : out-row group

    const float* W; const float* bias; float* dst; int chbase;
    const int och = oc * 64;
    if (och < 128)      { W = Wq; bias = bq; dst = g_Q; chbase = och; }
    else if (och < 256) { W = Wk; bias = bk; dst = g_K; chbase = och - 128; }
    else                { W = Wv; bias = bv; dst = g_V; chbase = och - 256; }

    __shared__ __align__(16) float Xs[32][128];
    __shared__ __align__(16) unsigned long long Wd[32][64];   // duplicated {w,w}

    const float* xb = x + (size_t)b * Cc * PXB + pxt * 128;

    unsigned long long acc[8][2];
    #pragma unroll
    for (int o = 0; o < 8; o++) { acc[o][0] = 0ULL; acc[o][1] = 0ULL; }

    for (int kt = 0; kt < 256; kt += 32) {
        // X tile: 32 channels x 128 px = 1024 float4 / 256 thr = 4 each
        #pragma unroll
        for (int i = 0; i < 4; i++) {
            int idx = tid + i * 256;
            int row = idx >> 5, col = idx & 31;
            float4 v = *(const float4*)(xb + (size_t)(kt + row) * PXB + col * 4);
            *(float4*)(&Xs[row][col * 4]) = v;
        }
        // W tile: 64 outs x 32 k, store duplicated [k][o]
        #pragma unroll
        for (int i = 0; i < 2; i++) {
            int idx = tid + i * 256;           // 0..511
            int o = idx >> 3, c4 = idx & 7;
            float4 v = *(const float4*)(W + (size_t)(chbase + o) * 256 + kt + c4 * 4);
            Wd[c4 * 4 + 0][o] = pk2(v.x, v.x);
            Wd[c4 * 4 + 1][o] = pk2(v.y, v.y);
            Wd[c4 * 4 + 2][o] = pk2(v.z, v.z);
            Wd[c4 * 4 + 3][o] = pk2(v.w, v.w);
        }
        __syncthreads();
        #pragma unroll 4
        for (int kk = 0; kk < 32; kk++) {
            ulonglong2 xv = *(const ulonglong2*)(&Xs[kk][lane * 4]);   // LDS.128
            const ulonglong2* wp = (const ulonglong2*)(&Wd[kk][r * 8]);
            ulonglong2 w01 = wp[0];   // LDS.128 broadcast x4
            ulonglong2 w23 = wp[1];
            ulonglong2 w45 = wp[2];
            ulonglong2 w67 = wp[3];
            fma2(acc[0][0], w01.x, xv.x); fma2(acc[0][1], w01.x, xv.y);
            fma2(acc[1][0], w01.y, xv.x); fma2(acc[1][1], w01.y, xv.y);
            fma2(acc[2][0], w23.x, xv.x); fma2(acc[2][1], w23.x, xv.y);
            fma2(acc[3][0], w23.y, xv.x); fma2(acc[3][1], w23.y, xv.y);
            fma2(acc[4][0], w45.x, xv.x); fma2(acc[4][1], w45.x, xv.y);
            fma2(acc[5][0], w45.y, xv.x); fma2(acc[5][1], w45.y, xv.y);
            fma2(acc[6][0], w67.x, xv.x); fma2(acc[6][1], w67.x, xv.y);
            fma2(acc[7][0], w67.y, xv.x); fma2(acc[7][1], w67.y, xv.y);
        }
        __syncthreads();
    }

    #pragma unroll
    for (int o = 0; o < 8; o++) {
        int ch = chbase + r * 8 + o;
        float bv_ = bias[ch];
        float4 outv;
        upk2(acc[o][0], outv.x, outv.y);
        upk2(acc[o][1], outv.z, outv.w);
        outv.x += bv_; outv.y += bv_; outv.z += bv_; outv.w += bv_;
        *(float4*)(dst + (size_t)(b * CRr + ch) * PXB + pxt * 128 + lane * 4) = outv;
    }
}

// =====================================================================
// Kernel 2: top-196 sorted descending per (n,t) row — warp-register bitonic.
// One warp per row, 32 values/lane. 8 rows per 256-thread block.
// Descending rule: at pair (i, i^j), i lower: keep max at i iff (i&k)==0.
// =====================================================================
#define NEG_INF __int_as_float(0xff800000)

// intra-thread stage: j >= 32. RJ = j>>5, KR = k>>5 (compile-time).
template<int RJ, int KR>
__device__ __forceinline__ void bt_intra(float* v) {
    #pragma unroll
    for (int rr = 0; rr < 32; rr++) {
        if ((rr & RJ) == 0) {
            const int r2 = rr | RJ;
            const bool up = ((rr & KR) == 0);   // keep max at rr
            float a = v[rr], bvv = v[r2];
            v[rr] = up ? fmaxf(a, bvv) : fminf(a, bvv);
            v[r2] = up ? fminf(a, bvv) : fmaxf(a, bvv);
        }
    }
}

// cross-lane stages: j = 16..1 for a pass with k>=32. KR = k>>5 (compile-time),
// so up = ((r & KR)==0) is compile-time per register.
template<int KR>
__device__ __forceinline__ void bt_shfl(float* v, unsigned lane) {
    for (int j = 16; j >= 1; j >>= 1) {
        const bool lower = ((lane & j) == 0);
        #pragma unroll
        for (int rr = 0; rr < 32; rr++) {
            float bvv = __shfl_xor_sync(0xffffffffu, v[rr], j);
            const bool up = ((rr & KR) == 0);
            const bool keep_max = (up == lower);
            v[rr] = keep_max ? fmaxf(v[rr], bvv) : fminf(v[rr], bvv);
        }
    }
}

__global__ __launch_bounds__(256) void topk_kernel()
{
    const unsigned lane = threadIdx.x & 31;
    const int wid = threadIdx.x >> 5;
    const int row = blockIdx.x * 8 + wid;          // 0..32767
    const int rl  = row & 16383;
    const float* src; float* dst;
    if (row < 16384) { src = g_Q; dst = g_Qtk; }
    else             { src = g_K; dst = g_Ktk; }
    const float* p = src + (size_t)rl * HWW;

    float v[32];
    #pragma unroll
    for (int rr = 0; rr < 32; rr++) {
        int idx = rr * 32 + (int)lane;
        v[rr] = (idx < HWW) ? p[idx] : NEG_INF;
    }

    // ---- k = 2..16: up depends on lane only ----
    for (int k = 2; k <= 16; k <<= 1) {
        for (int j = k >> 1; j >= 1; j >>= 1) {
            const bool eq = (((lane & k) == 0) == ((lane & j) == 0)); // keep_max
            #pragma unroll
            for (int rr = 0; rr < 32; rr++) {
                float bvv = __shfl_xor_sync(0xffffffffu, v[rr], j);
                v[rr] = eq ? fmaxf(v[rr], bvv) : fminf(v[rr], bvv);
            }
        }
    }
    // ---- k = 32 : up = ((r&1)==0) ----
    bt_shfl<1>(v, lane);
    // ---- k = 64 ----
    bt_intra<1, 2>(v);  bt_shfl<2>(v, lane);
    // ---- k = 128 ----
    bt_intra<2, 4>(v);  bt_intra<1, 4>(v);  bt_shfl<4>(v, lane);
    // ---- k = 256 ----
    bt_intra<4, 8>(v);  bt_intra<2, 8>(v);  bt_intra<1, 8>(v);  bt_shfl<8>(v, lane);
    // ---- k = 512 ----
    bt_intra<8, 16>(v); bt_intra<4, 16>(v); bt_intra<2, 16>(v); bt_intra<1, 16>(v);
    bt_shfl<16>(v, lane);
    // ---- k = 1024 (final, fully descending) ----
    bt_intra<16, 32>(v); bt_intra<8, 32>(v); bt_intra<4, 32>(v); bt_intra<2, 32>(v);
    bt_intra<1, 32>(v);  bt_shfl<32>(v, lane);

    // write top 196 (descending): indices 0..195 = r*32+lane
    float* q = dst + (size_t)rl * KTOP;
    #pragma unroll
    for (int rr = 0; rr < 6; rr++)
        q[rr * 32 + lane] = v[rr];
    if (lane < 4) q[192 + lane] = v[6];
}

// =====================================================================
// Kernel 3: per-n attention: corr = Qtk@Ktk^T (16x16), softmax, Y = attn@V
// grid = 1024, 256 threads.
// =====================================================================
__global__ __launch_bounds__(256) void attn_kernel()
{
    __shared__ float Qs[Tt * KTOP];
    __shared__ float Ks[Tt * KTOP];
    __shared__ float A[Tt * Tt];
    const int n   = blockIdx.x;
    const int tid = threadIdx.x;

    const float* qp = g_Qtk + (size_t)n * Tt * KTOP;
    const float* kp = g_Ktk + (size_t)n * Tt * KTOP;
    for (int i = tid; i < Tt * KTOP; i += 256) { Qs[i] = qp[i]; Ks[i] = kp[i]; }
    __syncthreads();

    {   // corr: one (t,s) per thread
        const int t = tid >> 4, s2 = tid & 15;
        float acc = 0.f;
        #pragma unroll 4
        for (int k = 0; k < KTOP; k++)
            acc += Qs[t * KTOP + k] * Ks[s2 * KTOP + k];
        A[t * 16 + s2] = acc;
    }
    __syncthreads();

    if (tid < 16) {   // softmax row tid
        float m = -1e30f;
        #pragma unroll
        for (int s2 = 0; s2 < 16; s2++) m = fmaxf(m, A[tid * 16 + s2]);
        float e[16], sum = 0.f;
        #pragma unroll
        for (int s2 = 0; s2 < 16; s2++) {
            e[s2] = __expf(A[tid * 16 + s2] - m);
            sum += e[s2];
        }
        float inv = 1.0f / sum;
        #pragma unroll
        for (int s2 = 0; s2 < 16; s2++) A[tid * 16 + s2] = e[s2] * inv;
    }
    __syncthreads();

    const float* vp = g_V + (size_t)n * PXB;
    float*       yp = g_Y + (size_t)n * PXB;
    for (int p = tid; p < HWW; p += 256) {
        float v[16];
        #pragma unroll
        for (int s2 = 0; s2 < 16; s2++) v[s2] = vp[s2 * HWW + p];
        #pragma unroll
        for (int t = 0; t < 16; t++) {
            float acc = 0.f;
            #pragma unroll
            for (int s2 = 0; s2 < 16; s2++) acc += A[t * 16 + s2] * v[s2];
            yp[t * HWW + p] = acc;
        }
    }
}

// =====================================================================
// Kernel 4: reconstruction: out = BN(Wr @ Y + br) + x
// grid (98, 4, 8), 256 threads. Same GEMM micro-structure as kernel 1.
// =====================================================================
__global__ __launch_bounds__(256) void recon_kernel(
    const float* __restrict__ x,
    const float* __restrict__ Wr, const float* __restrict__ br,
    const float* __restrict__ gamma, const float* __restrict__ beta,
    const float* __restrict__ bn_mean, const float* __restrict__ bn_var,
    float* __restrict__ out)
{
    const int pxt = blockIdx.x;
    const int oc  = blockIdx.y;            // 0..3 (chunks of 64 of 256)
    const int b   = blockIdx.z;
    const int tid = threadIdx.x;
    const int lane = tid & 31;
    const int r    = tid >> 5;
    const int och  = oc * 64;

    __shared__ __align__(16) float Ys[32][128];
    __shared__ __align__(16) unsigned long long Wd[32][64];

    const float* yb = g_Y + (size_t)b * CRr * PXB + pxt * 128;

    unsigned long long acc[8][2];
    #pragma unroll
    for (int o = 0; o < 8; o++) { acc[o][0] = 0ULL; acc[o][1] = 0ULL; }

    for (int kt = 0; kt < 128; kt += 32) {
        #pragma unroll
        for (int i = 0; i < 4; i++) {
            int idx = tid + i * 256;
            int row = idx >> 5, col = idx & 31;
            float4 v = *(const float4*)(yb + (size_t)(kt + row) * PXB + col * 4);
            *(float4*)(&Ys[row][col * 4]) = v;
        }
        #pragma unroll
        for (int i = 0; i < 2; i++) {
            int idx = tid + i * 256;
            int o = idx >> 3, c4 = idx & 7;
            float4 v = *(const float4*)(Wr + (size_t)(och + o) * CRr + kt + c4 * 4);
            Wd[c4 * 4 + 0][o] = pk2(v.x, v.x);
            Wd[c4 * 4 + 1][o] = pk2(v.y, v.y);
            Wd[c4 * 4 + 2][o] = pk2(v.z, v.z);
            Wd[c4 * 4 + 3][o] = pk2(v.w, v.w);
        }
        __syncthreads();
        #pragma unroll 4
        for (int kk = 0; kk < 32; kk++) {
            ulonglong2 yv = *(const ulonglong2*)(&Ys[kk][lane * 4]);
            const ulonglong2* wp = (const ulonglong2*)(&Wd[kk][r * 8]);
            ulonglong2 w01 = wp[0];
            ulonglong2 w23 = wp[1];
            ulonglong2 w45 = wp[2];
            ulonglong2 w67 = wp[3];
            fma2(acc[0][0], w01.x, yv.x); fma2(acc[0][1], w01.x, yv.y);
            fma2(acc[1][0], w01.y, yv.x); fma2(acc[1][1], w01.y, yv.y);
            fma2(acc[2][0], w23.x, yv.x); fma2(acc[2][1], w23.x, yv.y);
            fma2(acc[3][0], w23.y, yv.x); fma2(acc[3][1], w23.y, yv.y);
            fma2(acc[4][0], w45.x, yv.x); fma2(acc[4][1], w45.x, yv.y);
            fma2(acc[5][0], w45.y, yv.x); fma2(acc[5][1], w45.y, yv.y);
            fma2(acc[6][0], w67.x, yv.x); fma2(acc[6][1], w67.x, yv.y);
            fma2(acc[7][0], w67.y, yv.x); fma2(acc[7][1], w67.y, yv.y);
        }
        __syncthreads();
    }

    #pragma unroll
    for (int o = 0; o < 8; o++) {
        int ch = och + r * 8 + o;
        float sc = gamma[ch] * rsqrtf(bn_var[ch] + 1e-5f);
        float c0 = sc * br[ch] + beta[ch] - bn_mean[ch] * sc;
        size_t idx = (size_t)(b * Cc + ch) * PXB + pxt * 128 + lane * 4;
        float4 xv = *(const float4*)(x + idx);
        float y0, y1, y2, y3;
        upk2(acc[o][0], y0, y1);
        upk2(acc[o][1], y2, y3);
        float4 ov;
        ov.x = sc * y0 + c0 + xv.x;
        ov.y = sc * y1 + c0 + xv.y;
        ov.z = sc * y2 + c0 + xv.z;
        ov.w = sc * y3 + c0 + xv.w;
        *(float4*)(out + idx) = ov;
    }
}

// =====================================================================
extern "C" void kernel_launch(void* const* d_in, const int* in_sizes, int n_in,
                              void* d_out, int out_size)
{
    const float* x       = (const float*)d_in[0];
    const float* Wq      = (const float*)d_in[1];
    const float* bq      = (const float*)d_in[2];
    const float* Wk      = (const float*)d_in[3];
    const float* bk      = (const float*)d_in[4];
    const float* Wv      = (const float*)d_in[5];
    const float* bv      = (const float*)d_in[6];
    const float* Wr      = (const float*)d_in[7];
    const float* br      = (const float*)d_in[8];
    const float* gamma   = (const float*)d_in[9];
    const float* beta    = (const float*)d_in[10];
    const float* bn_mean = (const float*)d_in[11];
    const float* bn_var  = (const float*)d_in[12];
    float* out = (float*)d_out;

    qkv_kernel<<<dim3(98, 6, Bb), 256>>>(x, Wq, bq, Wk, bk, Wv, bv);
    topk_kernel<<<(2 * NN * Tt) / 8, 256>>>();
    attn_kernel<<<NN, 256>>>();
    recon_kernel<<<dim3(98, 4, Bb), 256>>>(x, Wr, br, gamma, beta,
                                           bn_mean, bn_var, out);
}

// round 5
// speedup vs baseline: 1.9969x; 1.1471x over previous
#include <cuda_runtime.h>
#include <cstdint>

#define Bb   8
#define Cc   256
#define CRr  128
#define Tt   16
#define HWW  784
#define PXB  (Tt * HWW)        // 12544 pixels per (b, channel) slab
#define KTOP 196
#define NN   (Bb * CRr)        // 1024 attention rows

// ---------------- scratch (device globals; no allocation allowed) ----------------
__device__ float g_Q[NN * PXB];        // [n][t][hw]
__device__ float g_K[NN * PXB];
__device__ float g_V[NN * PXB];
__device__ float g_Qtk[NN * Tt * KTOP];
__device__ float g_Ktk[NN * Tt * KTOP];
__device__ float g_Y[NN * PXB];

// ---------------- f32x2 helpers ----------------
__device__ __forceinline__ void fma2(unsigned long long& c, unsigned long long a,
                                     unsigned long long b) {
    asm("fma.rn.f32x2 %0, %1, %2, %0;" : "+l"(c) : "l"(a), "l"(b));
}
__device__ __forceinline__ unsigned long long pk2(float lo, float hi) {
    unsigned long long r;
    asm("mov.b64 %0, {%1, %2};" : "=l"(r) : "f"(lo), "f"(hi));
    return r;
}
__device__ __forceinline__ void upk2(unsigned long long v, float& lo, float& hi) {
    asm("mov.b64 {%0, %1}, %2;" : "=f"(lo), "=f"(hi) : "l"(v));
}

// =====================================================================
// Kernel 1: QKV projection. out[384, px] = W[384,256] @ x[256, px] + bias
// grid (49 px-tiles of 256, 6 out-chunks of 64, 8 batches), 256 threads.
// Per-thread: 8 outs x 8 px (f32x2-packed).
// =====================================================================
__global__ __launch_bounds__(256) void qkv_kernel(
    const float* __restrict__ x,
    const float* __restrict__ Wq, const float* __restrict__ bq,
    const float* __restrict__ Wk, const float* __restrict__ bk,
    const float* __restrict__ Wv, const float* __restrict__ bv)
{
    const int pxt = blockIdx.x;            // 0..48
    const int oc  = blockIdx.y;            // 0..5
    const int b   = blockIdx.z;            // 0..7
    const int tid = threadIdx.x;
    const int lane = tid & 31;
    const int r    = tid >> 5;             // 0..7 : out-row group

    const float* W; const float* bias; float* dst; int chbase;
    const int och = oc * 64;
    if (och < 128)      { W = Wq; bias = bq; dst = g_Q; chbase = och; }
    else if (och < 256) { W = Wk; bias = bk; dst = g_K; chbase = och - 128; }
    else                { W = Wv; bias = bv; dst = g_V; chbase = och - 256; }

    __shared__ __align__(16) float Xs[32][256];                 // 32 KB
    __shared__ __align__(16) unsigned long long Wd[32][64];     // 16 KB

    const float* xb = x + (size_t)b * Cc * PXB + pxt * 256;

    unsigned long long acc[8][4];
    #pragma unroll
    for (int o = 0; o < 8; o++)
        #pragma unroll
        for (int h = 0; h < 4; h++) acc[o][h] = 0ULL;

    for (int kt = 0; kt < 256; kt += 32) {
        // X tile: 32 channels x 256 px = 2048 float4 / 256 thr = 8 each
        #pragma unroll
        for (int i = 0; i < 8; i++) {
            int idx = tid + i * 256;
            int row = idx >> 6, col = idx & 63;
            float4 v = *(const float4*)(xb + (size_t)(kt + row) * PXB + col * 4);
            *(float4*)(&Xs[row][col * 4]) = v;
        }
        // W tile: 64 outs x 32 k, store duplicated [k][o]
        #pragma unroll
        for (int i = 0; i < 2; i++) {
            int idx = tid + i * 256;           // 0..511
            int o = idx >> 3, c4 = idx & 7;
            float4 v = *(const float4*)(W + (size_t)(chbase + o) * 256 + kt + c4 * 4);
            Wd[c4 * 4 + 0][o] = pk2(v.x, v.x);
            Wd[c4 * 4 + 1][o] = pk2(v.y, v.y);
            Wd[c4 * 4 + 2][o] = pk2(v.z, v.z);
            Wd[c4 * 4 + 3][o] = pk2(v.w, v.w);
        }
        __syncthreads();
        #pragma unroll 4
        for (int kk = 0; kk < 32; kk++) {
            ulonglong2 xa = *(const ulonglong2*)(&Xs[kk][lane * 4]);
            ulonglong2 xc = *(const ulonglong2*)(&Xs[kk][128 + lane * 4]);
            const ulonglong2* wp = (const ulonglong2*)(&Wd[kk][r * 8]);
            ulonglong2 w01 = wp[0];
            ulonglong2 w23 = wp[1];
            ulonglong2 w45 = wp[2];
            ulonglong2 w67 = wp[3];
            fma2(acc[0][0], w01.x, xa.x); fma2(acc[0][1], w01.x, xa.y);
            fma2(acc[0][2], w01.x, xc.x); fma2(acc[0][3], w01.x, xc.y);
            fma2(acc[1][0], w01.y, xa.x); fma2(acc[1][1], w01.y, xa.y);
            fma2(acc[1][2], w01.y, xc.x); fma2(acc[1][3], w01.y, xc.y);
            fma2(acc[2][0], w23.x, xa.x); fma2(acc[2][1], w23.x, xa.y);
            fma2(acc[2][2], w23.x, xc.x); fma2(acc[2][3], w23.x, xc.y);
            fma2(acc[3][0], w23.y, xa.x); fma2(acc[3][1], w23.y, xa.y);
            fma2(acc[3][2], w23.y, xc.x); fma2(acc[3][3], w23.y, xc.y);
            fma2(acc[4][0], w45.x, xa.x); fma2(acc[4][1], w45.x, xa.y);
            fma2(acc[4][2], w45.x, xc.x); fma2(acc[4][3], w45.x, xc.y);
            fma2(acc[5][0], w45.y, xa.x); fma2(acc[5][1], w45.y, xa.y);
            fma2(acc[5][2], w45.y, xc.x); fma2(acc[5][3], w45.y, xc.y);
            fma2(acc[6][0], w67.x, xa.x); fma2(acc[6][1], w67.x, xa.y);
            fma2(acc[6][2], w67.x, xc.x); fma2(acc[6][3], w67.x, xc.y);
            fma2(acc[7][0], w67.y, xa.x); fma2(acc[7][1], w67.y, xa.y);
            fma2(acc[7][2], w67.y, xc.x); fma2(acc[7][3], w67.y, xc.y);
        }
        __syncthreads();
    }

    #pragma unroll
    for (int o = 0; o < 8; o++) {
        int ch = chbase + r * 8 + o;
        float bv_ = bias[ch];
        float* dp = dst + (size_t)(b * CRr + ch) * PXB + pxt * 256;
        float4 o0, o1;
        upk2(acc[o][0], o0.x, o0.y); upk2(acc[o][1], o0.z, o0.w);
        upk2(acc[o][2], o1.x, o1.y); upk2(acc[o][3], o1.z, o1.w);
        o0.x += bv_; o0.y += bv_; o0.z += bv_; o0.w += bv_;
        o1.x += bv_; o1.y += bv_; o1.z += bv_; o1.w += bv_;
        *(float4*)(dp + lane * 4)       = o0;
        *(float4*)(dp + 128 + lane * 4) = o1;
    }
}

// =====================================================================
// Kernel 2: top-196 sorted descending per (n,t) row — warp-register bitonic.
// One warp per row, 32 values/lane. 8 rows per 256-thread block.
// =====================================================================
#define NEG_INF __int_as_float(0xff800000)

template<int RJ, int KR>
__device__ __forceinline__ void bt_intra(float* v) {
    #pragma unroll
    for (int rr = 0; rr < 32; rr++) {
        if ((rr & RJ) == 0) {
            const int r2 = rr | RJ;
            const bool up = ((rr & KR) == 0);   // keep max at rr
            float a = v[rr], bvv = v[r2];
            v[rr] = up ? fmaxf(a, bvv) : fminf(a, bvv);
            v[r2] = up ? fminf(a, bvv) : fmaxf(a, bvv);
        }
    }
}

template<int KR>
__device__ __forceinline__ void bt_shfl(float* v, unsigned lane) {
    for (int j = 16; j >= 1; j >>= 1) {
        const bool lower = ((lane & j) == 0);
        #pragma unroll
        for (int rr = 0; rr < 32; rr++) {
            float bvv = __shfl_xor_sync(0xffffffffu, v[rr], j);
            const bool up = ((rr & KR) == 0);
            const bool keep_max = (up == lower);
            v[rr] = keep_max ? fmaxf(v[rr], bvv) : fminf(v[rr], bvv);
        }
    }
}

__global__ __launch_bounds__(256) void topk_kernel()
{
    const unsigned lane = threadIdx.x & 31;
    const int wid = threadIdx.x >> 5;
    const int row = blockIdx.x * 8 + wid;          // 0..32767
    const int rl  = row & 16383;
    const float* src; float* dst;
    if (row < 16384) { src = g_Q; dst = g_Qtk; }
    else             { src = g_K; dst = g_Ktk; }
    const float* p = src + (size_t)rl * HWW;

    float v[32];
    #pragma unroll
    for (int rr = 0; rr < 32; rr++) {
        int idx = rr * 32 + (int)lane;
        v[rr] = (idx < HWW) ? p[idx] : NEG_INF;
    }

    for (int k = 2; k <= 16; k <<= 1) {
        for (int j = k >> 1; j >= 1; j >>= 1) {
            const bool eq = (((lane & k) == 0) == ((lane & j) == 0)); // keep_max
            #pragma unroll
            for (int rr = 0; rr < 32; rr++) {
                float bvv = __shfl_xor_sync(0xffffffffu, v[rr], j);
                v[rr] = eq ? fmaxf(v[rr], bvv) : fminf(v[rr], bvv);
            }
        }
    }
    bt_shfl<1>(v, lane);
    bt_intra<1, 2>(v);  bt_shfl<2>(v, lane);
    bt_intra<2, 4>(v);  bt_intra<1, 4>(v);  bt_shfl<4>(v, lane);
    bt_intra<4, 8>(v);  bt_intra<2, 8>(v);  bt_intra<1, 8>(v);  bt_shfl<8>(v, lane);
    bt_intra<8, 16>(v); bt_intra<4, 16>(v); bt_intra<2, 16>(v); bt_intra<1, 16>(v);
    bt_shfl<16>(v, lane);
    bt_intra<16, 32>(v); bt_intra<8, 32>(v); bt_intra<4, 32>(v); bt_intra<2, 32>(v);
    bt_intra<1, 32>(v);  bt_shfl<32>(v, lane);

    float* q = dst + (size_t)rl * KTOP;
    #pragma unroll
    for (int rr = 0; rr < 6; rr++)
        q[rr * 32 + lane] = v[rr];
    if (lane < 4) q[192 + lane] = v[6];
}

// =====================================================================
// Kernel 3: per-n attention: corr = Qtk@Ktk^T (16x16), softmax, Y = attn@V
// grid = 1024, 256 threads.
// =====================================================================
__global__ __launch_bounds__(256) void attn_kernel()
{
    __shared__ float Qs[Tt * KTOP];
    __shared__ float Ks[Tt * KTOP];
    __shared__ float A[Tt * Tt];
    const int n   = blockIdx.x;
    const int tid = threadIdx.x;

    const float* qp = g_Qtk + (size_t)n * Tt * KTOP;
    const float* kp = g_Ktk + (size_t)n * Tt * KTOP;
    for (int i = tid; i < Tt * KTOP; i += 256) { Qs[i] = qp[i]; Ks[i] = kp[i]; }
    __syncthreads();

    {   // corr: one (t,s) per thread
        const int t = tid >> 4, s2 = tid & 15;
        float acc = 0.f;
        #pragma unroll 4
        for (int k = 0; k < KTOP; k++)
            acc += Qs[t * KTOP + k] * Ks[s2 * KTOP + k];
        A[t * 16 + s2] = acc;
    }
    __syncthreads();

    if (tid < 16) {   // softmax row tid
        float m = -1e30f;
        #pragma unroll
        for (int s2 = 0; s2 < 16; s2++) m = fmaxf(m, A[tid * 16 + s2]);
        float e[16], sum = 0.f;
        #pragma unroll
        for (int s2 = 0; s2 < 16; s2++) {
            e[s2] = __expf(A[tid * 16 + s2] - m);
            sum += e[s2];
        }
        float inv = 1.0f / sum;
        #pragma unroll
        for (int s2 = 0; s2 < 16; s2++) A[tid * 16 + s2] = e[s2] * inv;
    }
    __syncthreads();

    const float* vp = g_V + (size_t)n * PXB;
    float*       yp = g_Y + (size_t)n * PXB;
    for (int p = tid; p < HWW; p += 256) {
        float v[16];
        #pragma unroll
        for (int s2 = 0; s2 < 16; s2++) v[s2] = vp[s2 * HWW + p];
        #pragma unroll
        for (int t = 0; t < 16; t++) {
            float acc = 0.f;
            #pragma unroll
            for (int s2 = 0; s2 < 16; s2++) acc += A[t * 16 + s2] * v[s2];
            yp[t * HWW + p] = acc;
        }
    }
}

// =====================================================================
// Kernel 4: reconstruction: out = BN(Wr @ Y + br) + x
// grid (49, 4, 8), 256 threads. 8 outs x 8 px per thread.
// =====================================================================
__global__ __launch_bounds__(256) void recon_kernel(
    const float* __restrict__ x,
    const float* __restrict__ Wr, const float* __restrict__ br,
    const float* __restrict__ gamma, const float* __restrict__ beta,
    const float* __restrict__ bn_mean, const float* __restrict__ bn_var,
    float* __restrict__ out)
{
    const int pxt = blockIdx.x;            // 0..48
    const int oc  = blockIdx.y;            // 0..3
    const int b   = blockIdx.z;
    const int tid = threadIdx.x;
    const int lane = tid & 31;
    const int r    = tid >> 5;
    const int och  = oc * 64;

    __shared__ __align__(16) float Ys[32][256];
    __shared__ __align__(16) unsigned long long Wd[32][64];

    const float* yb = g_Y + (size_t)b * CRr * PXB + pxt * 256;

    unsigned long long acc[8][4];
    #pragma unroll
    for (int o = 0; o < 8; o++)
        #pragma unroll
        for (int h = 0; h < 4; h++) acc[o][h] = 0ULL;

    for (int kt = 0; kt < 128; kt += 32) {
        #pragma unroll
        for (int i = 0; i < 8; i++) {
            int idx = tid + i * 256;
            int row = idx >> 6, col = idx & 63;
            float4 v = *(const float4*)(yb + (size_t)(kt + row) * PXB + col * 4);
            *(float4*)(&Ys[row][col * 4]) = v;
        }
        #pragma unroll
        for (int i = 0; i < 2; i++) {
            int idx = tid + i * 256;
            int o = idx >> 3, c4 = idx & 7;
            float4 v = *(const float4*)(Wr + (size_t)(och + o) * CRr + kt + c4 * 4);
            Wd[c4 * 4 + 0][o] = pk2(v.x, v.x);
            Wd[c4 * 4 + 1][o] = pk2(v.y, v.y);
            Wd[c4 * 4 + 2][o] = pk2(v.z, v.z);
            Wd[c4 * 4 + 3][o] = pk2(v.w, v.w);
        }
        __syncthreads();
        #pragma unroll 4
        for (int kk = 0; kk < 32; kk++) {
            ulonglong2 xa = *(const ulonglong2*)(&Ys[kk][lane * 4]);
            ulonglong2 xc = *(const ulonglong2*)(&Ys[kk][128 + lane * 4]);
            const ulonglong2* wp = (const ulonglong2*)(&Wd[kk][r * 8]);
            ulonglong2 w01 = wp[0];
            ulonglong2 w23 = wp[1];
            ulonglong2 w45 = wp[2];
            ulonglong2 w67 = wp[3];
            fma2(acc[0][0], w01.x, xa.x); fma2(acc[0][1], w01.x, xa.y);
            fma2(acc[0][2], w01.x, xc.x); fma2(acc[0][3], w01.x, xc.y);
            fma2(acc[1][0], w01.y, xa.x); fma2(acc[1][1], w01.y, xa.y);
            fma2(acc[1][2], w01.y, xc.x); fma2(acc[1][3], w01.y, xc.y);
            fma2(acc[2][0], w23.x, xa.x); fma2(acc[2][1], w23.x, xa.y);
            fma2(acc[2][2], w23.x, xc.x); fma2(acc[2][3], w23.x, xc.y);
            fma2(acc[3][0], w23.y, xa.x); fma2(acc[3][1], w23.y, xa.y);
            fma2(acc[3][2], w23.y, xc.x); fma2(acc[3][3], w23.y, xc.y);
            fma2(acc[4][0], w45.x, xa.x); fma2(acc[4][1], w45.x, xa.y);
            fma2(acc[4][2], w45.x, xc.x); fma2(acc[4][3], w45.x, xc.y);
            fma2(acc[5][0], w45.y, xa.x); fma2(acc[5][1], w45.y, xa.y);
            fma2(acc[5][2], w45.y, xc.x); fma2(acc[5][3], w45.y, xc.y);
            fma2(acc[6][0], w67.x, xa.x); fma2(acc[6][1], w67.x, xa.y);
            fma2(acc[6][2], w67.x, xc.x); fma2(acc[6][3], w67.x, xc.y);
            fma2(acc[7][0], w67.y, xa.x); fma2(acc[7][1], w67.y, xa.y);
            fma2(acc[7][2], w67.y, xc.x); fma2(acc[7][3], w67.y, xc.y);
        }
        __syncthreads();
    }

    #pragma unroll
    for (int o = 0; o < 8; o++) {
        int ch = och + r * 8 + o;
        float sc = gamma[ch] * rsqrtf(bn_var[ch] + 1e-5f);
        float c0 = sc * br[ch] + beta[ch] - bn_mean[ch] * sc;
        size_t base = (size_t)(b * Cc + ch) * PXB + pxt * 256;
        float4 xv0 = *(const float4*)(x + base + lane * 4);
        float4 xv1 = *(const float4*)(x + base + 128 + lane * 4);
        float y0, y1, y2, y3, y4, y5, y6, y7;
        upk2(acc[o][0], y0, y1); upk2(acc[o][1], y2, y3);
        upk2(acc[o][2], y4, y5); upk2(acc[o][3], y6, y7);
        float4 ov0, ov1;
        ov0.x = sc * y0 + c0 + xv0.x;
        ov0.y = sc * y1 + c0 + xv0.y;
        ov0.z = sc * y2 + c0 + xv0.z;
        ov0.w = sc * y3 + c0 + xv0.w;
        ov1.x = sc * y4 + c0 + xv1.x;
        ov1.y = sc * y5 + c0 + xv1.y;
        ov1.z = sc * y6 + c0 + xv1.z;
        ov1.w = sc * y7 + c0 + xv1.w;
        *(float4*)(out + base + lane * 4)       = ov0;
        *(float4*)(out + base + 128 + lane * 4) = ov1;
    }
}

// =====================================================================
extern "C" void kernel_launch(void* const* d_in, const int* in_sizes, int n_in,
                              void* d_out, int out_size)
{
    const float* x       = (const float*)d_in[0];
    const float* Wq      = (const float*)d_in[1];
    const float* bq      = (const float*)d_in[2];
    const float* Wk      = (const float*)d_in[3];
    const float* bk      = (const float*)d_in[4];
    const float* Wv      = (const float*)d_in[5];
    const float* bv      = (const float*)d_in[6];
    const float* Wr      = (const float*)d_in[7];
    const float* br      = (const float*)d_in[8];
    const float* gamma   = (const float*)d_in[9];
    const float* beta    = (const float*)d_in[10];
    const float* bn_mean = (const float*)d_in[11];
    const float* bn_var  = (const float*)d_in[12];
    float* out = (float*)d_out;

    qkv_kernel<<<dim3(49, 6, Bb), 256>>>(x, Wq, bq, Wk, bk, Wv, bv);
    topk_kernel<<<(2 * NN * Tt) / 8, 256>>>();
    attn_kernel<<<NN, 256>>>();
    recon_kernel<<<dim3(49, 4, Bb), 256>>>(x, Wr, br, gamma, beta,
                                           bn_mean, bn_var, out);
}

// round 7
// speedup vs baseline: 2.0356x; 1.0193x over previous
#include <cuda_runtime.h>
#include <cstdint>

#define Bb   8
#define Cc   256
#define CRr  128
#define Tt   16
#define HWW  784
#define PXB  (Tt * HWW)        // 12544 pixels per (b, channel) slab
#define KTOP 196
#define NN   (Bb * CRr)        // 1024 attention rows

// ---------------- scratch (device globals; no allocation allowed) ----------------
__device__ float g_Q[NN * PXB];        // [n][t][hw]
__device__ float g_K[NN * PXB];
__device__ float g_V[NN * PXB];
__device__ float g_Qtk[NN * Tt * KTOP];
__device__ float g_Ktk[NN * Tt * KTOP];
__device__ float g_Y[NN * PXB];

// ---------------- f32x2 helpers ----------------
__device__ __forceinline__ void fma2(unsigned long long& c, unsigned long long a,
                                     unsigned long long b) {
    asm("fma.rn.f32x2 %0, %1, %2, %0;" : "+l"(c) : "l"(a), "l"(b));
}
__device__ __forceinline__ unsigned long long pk2(float lo, float hi) {
    unsigned long long r;
    asm("mov.b64 %0, {%1, %2};" : "=l"(r) : "f"(lo), "f"(hi));
    return r;
}
__device__ __forceinline__ void upk2(unsigned long long v, float& lo, float& hi) {
    asm("mov.b64 {%0, %1}, %2;" : "=f"(lo), "=f"(hi) : "l"(v));
}

// =====================================================================
// Kernel 1: QKV projection. out[384, px] = W[384,256] @ x[256, px] + bias
// grid (49 px-tiles of 256, 6 out-chunks of 64, 8 batches), 256 threads.
// Per-thread: 8 outs x 8 px (f32x2-packed). 2 blocks/SM (reg cap 128).
// =====================================================================
__global__ __launch_bounds__(256, 2) void qkv_kernel(
    const float* __restrict__ x,
    const float* __restrict__ Wq, const float* __restrict__ bq,
    const float* __restrict__ Wk, const float* __restrict__ bk,
    const float* __restrict__ Wv, const float* __restrict__ bv)
{
    const int pxt = blockIdx.x;            // 0..48
    const int oc  = blockIdx.y;            // 0..5
    const int b   = blockIdx.z;            // 0..7
    const int tid = threadIdx.x;
    const int lane = tid & 31;
    const int r    = tid >> 5;             // 0..7 : out-row group

    const float* W; const float* bias; float* dst; int chbase;
    const int och = oc * 64;
    if (och < 128)      { W = Wq; bias = bq; dst = g_Q; chbase = och; }
    else if (och < 256) { W = Wk; bias = bk; dst = g_K; chbase = och - 128; }
    else                { W = Wv; bias = bv; dst = g_V; chbase = och - 256; }

    __shared__ __align__(16) float Xs[32][256];                 // 32 KB
    __shared__ __align__(16) unsigned long long Wd[32][64];     // 16 KB

    const float* xb = x + (size_t)b * Cc * PXB + pxt * 256;

    unsigned long long acc[8][4];
    #pragma unroll
    for (int o = 0; o < 8; o++)
        #pragma unroll
        for (int h = 0; h < 4; h++) acc[o][h] = 0ULL;

    for (int kt = 0; kt < 256; kt += 32) {
        // X tile: 32 channels x 256 px = 2048 float4 / 256 thr = 8 each
        #pragma unroll 4
        for (int i = 0; i < 8; i++) {
            int idx = tid + i * 256;
            int row = idx >> 6, col = idx & 63;
            float4 v = *(const float4*)(xb + (size_t)(kt + row) * PXB + col * 4);
            *(float4*)(&Xs[row][col * 4]) = v;
        }
        // W tile: 64 outs x 32 k, store duplicated [k][o]
        #pragma unroll
        for (int i = 0; i < 2; i++) {
            int idx = tid + i * 256;           // 0..511
            int o = idx >> 3, c4 = idx & 7;
            float4 v = *(const float4*)(W + (size_t)(chbase + o) * 256 + kt + c4 * 4);
            Wd[c4 * 4 + 0][o] = pk2(v.x, v.x);
            Wd[c4 * 4 + 1][o] = pk2(v.y, v.y);
            Wd[c4 * 4 + 2][o] = pk2(v.z, v.z);
            Wd[c4 * 4 + 3][o] = pk2(v.w, v.w);
        }
        __syncthreads();
        #pragma unroll 2
        for (int kk = 0; kk < 32; kk++) {
            ulonglong2 xa = *(const ulonglong2*)(&Xs[kk][lane * 4]);
            ulonglong2 xc = *(const ulonglong2*)(&Xs[kk][128 + lane * 4]);
            const ulonglong2* wp = (const ulonglong2*)(&Wd[kk][r * 8]);
            ulonglong2 w01 = wp[0];
            ulonglong2 w23 = wp[1];
            ulonglong2 w45 = wp[2];
            ulonglong2 w67 = wp[3];
            fma2(acc[0][0], w01.x, xa.x); fma2(acc[0][1], w01.x, xa.y);
            fma2(acc[0][2], w01.x, xc.x); fma2(acc[0][3], w01.x, xc.y);
            fma2(acc[1][0], w01.y, xa.x); fma2(acc[1][1], w01.y, xa.y);
            fma2(acc[1][2], w01.y, xc.x); fma2(acc[1][3], w01.y, xc.y);
            fma2(acc[2][0], w23.x, xa.x); fma2(acc[2][1], w23.x, xa.y);
            fma2(acc[2][2], w23.x, xc.x); fma2(acc[2][3], w23.x, xc.y);
            fma2(acc[3][0], w23.y, xa.x); fma2(acc[3][1], w23.y, xa.y);
            fma2(acc[3][2], w23.y, xc.x); fma2(acc[3][3], w23.y, xc.y);
            fma2(acc[4][0], w45.x, xa.x); fma2(acc[4][1], w45.x, xa.y);
            fma2(acc[4][2], w45.x, xc.x); fma2(acc[4][3], w45.x, xc.y);
            fma2(acc[5][0], w45.y, xa.x); fma2(acc[5][1], w45.y, xa.y);
            fma2(acc[5][2], w45.y, xc.x); fma2(acc[5][3], w45.y, xc.y);
            fma2(acc[6][0], w67.x, xa.x); fma2(acc[6][1], w67.x, xa.y);
            fma2(acc[6][2], w67.x, xc.x); fma2(acc[6][3], w67.x, xc.y);
            fma2(acc[7][0], w67.y, xa.x); fma2(acc[7][1], w67.y, xa.y);
            fma2(acc[7][2], w67.y, xc.x); fma2(acc[7][3], w67.y, xc.y);
        }
        __syncthreads();
    }

    #pragma unroll
    for (int o = 0; o < 8; o++) {
        int ch = chbase + r * 8 + o;
        float bv_ = bias[ch];
        float* dp = dst + (size_t)(b * CRr + ch) * PXB + pxt * 256;
        float4 o0, o1;
        upk2(acc[o][0], o0.x, o0.y); upk2(acc[o][1], o0.z, o0.w);
        upk2(acc[o][2], o1.x, o1.y); upk2(acc[o][3], o1.z, o1.w);
        o0.x += bv_; o0.y += bv_; o0.z += bv_; o0.w += bv_;
        o1.x += bv_; o1.y += bv_; o1.z += bv_; o1.w += bv_;
        *(float4*)(dp + lane * 4)       = o0;
        *(float4*)(dp + 128 + lane * 4) = o1;
    }
}

// =====================================================================
// Kernel 2: top-196 sorted descending per (n,t) row — warp-register bitonic.
// One warp per row, 32 values/lane. 8 rows per 256-thread block.
// =====================================================================
#define NEG_INF __int_as_float(0xff800000)

template<int RJ, int KR>
__device__ __forceinline__ void bt_intra(float* v) {
    #pragma unroll
    for (int rr = 0; rr < 32; rr++) {
        if ((rr & RJ) == 0) {
            const int r2 = rr | RJ;
            const bool up = ((rr & KR) == 0);   // keep max at rr
            float a = v[rr], bvv = v[r2];
            v[rr] = up ? fmaxf(a, bvv) : fminf(a, bvv);
            v[r2] = up ? fminf(a, bvv) : fmaxf(a, bvv);
        }
    }
}

template<int KR>
__device__ __forceinline__ void bt_shfl(float* v, unsigned lane) {
    for (int j = 16; j >= 1; j >>= 1) {
        const bool lower = ((lane & j) == 0);
        #pragma unroll
        for (int rr = 0; rr < 32; rr++) {
            float bvv = __shfl_xor_sync(0xffffffffu, v[rr], j);
            const bool up = ((rr & KR) == 0);
            const bool keep_max = (up == lower);
            v[rr] = keep_max ? fmaxf(v[rr], bvv) : fminf(v[rr], bvv);
        }
    }
}

__global__ __launch_bounds__(256) void topk_kernel()
{
    const unsigned lane = threadIdx.x & 31;
    const int wid = threadIdx.x >> 5;
    const int row = blockIdx.x * 8 + wid;          // 0..32767
    const int rl  = row & 16383;
    const float* src; float* dst;
    if (row < 16384) { src = g_Q; dst = g_Qtk; }
    else             { src = g_K; dst = g_Ktk; }
    const float* p = src + (size_t)rl * HWW;

    float v[32];
    #pragma unroll
    for (int rr = 0; rr < 32; rr++) {
        int idx = rr * 32 + (int)lane;
        v[rr] = (idx < HWW) ? p[idx] : NEG_INF;
    }

    for (int k = 2; k <= 16; k <<= 1) {
        for (int j = k >> 1; j >= 1; j >>= 1) {
            const bool eq = (((lane & k) == 0) == ((lane & j) == 0)); // keep_max
            #pragma unroll
            for (int rr = 0; rr < 32; rr++) {
                float bvv = __shfl_xor_sync(0xffffffffu, v[rr], j);
                v[rr] = eq ? fmaxf(v[rr], bvv) : fminf(v[rr], bvv);
            }
        }
    }
    bt_shfl<1>(v, lane);
    bt_intra<1, 2>(v);  bt_shfl<2>(v, lane);
    bt_intra<2, 4>(v);  bt_intra<1, 4>(v);  bt_shfl<4>(v, lane);
    bt_intra<4, 8>(v);  bt_intra<2, 8>(v);  bt_intra<1, 8>(v);  bt_shfl<8>(v, lane);
    bt_intra<8, 16>(v); bt_intra<4, 16>(v); bt_intra<2, 16>(v); bt_intra<1, 16>(v);
    bt_shfl<16>(v, lane);
    bt_intra<16, 32>(v); bt_intra<8, 32>(v); bt_intra<4, 32>(v); bt_intra<2, 32>(v);
    bt_intra<1, 32>(v);  bt_shfl<32>(v, lane);

    float* q = dst + (size_t)rl * KTOP;
    #pragma unroll
    for (int rr = 0; rr < 6; rr++)
        q[rr * 32 + lane] = v[rr];
    if (lane < 4) q[192 + lane] = v[6];
}

// =====================================================================
// Kernel 3: per-n attention: corr = Qtk@Ktk^T (16x16), softmax, Y = attn@V
// grid = 1024, 256 threads.
// =====================================================================
__global__ __launch_bounds__(256) void attn_kernel()
{
    __shared__ float Qs[Tt * KTOP];
    __shared__ float Ks[Tt * KTOP];
    __shared__ float A[Tt * Tt];
    const int n   = blockIdx.x;
    const int tid = threadIdx.x;

    const float* qp = g_Qtk + (size_t)n * Tt * KTOP;
    const float* kp = g_Ktk + (size_t)n * Tt * KTOP;
    for (int i = tid; i < Tt * KTOP; i += 256) { Qs[i] = qp[i]; Ks[i] = kp[i]; }
    __syncthreads();

    {   // corr: one (t,s) per thread
        const int t = tid >> 4, s2 = tid & 15;
        float acc = 0.f;
        #pragma unroll 4
        for (int k = 0; k < KTOP; k++)
            acc += Qs[t * KTOP + k] * Ks[s2 * KTOP + k];
        A[t * 16 + s2] = acc;
    }
    __syncthreads();

    if (tid < 16) {   // softmax row tid
        float m = -1e30f;
        #pragma unroll
        for (int s2 = 0; s2 < 16; s2++) m = fmaxf(m, A[tid * 16 + s2]);
        float e[16], sum = 0.f;
        #pragma unroll
        for (int s2 = 0; s2 < 16; s2++) {
            e[s2] = __expf(A[tid * 16 + s2] - m);
            sum += e[s2];
        }
        float inv = 1.0f / sum;
        #pragma unroll
        for (int s2 = 0; s2 < 16; s2++) A[tid * 16 + s2] = e[s2] * inv;
    }
    __syncthreads();

    const float* vp = g_V + (size_t)n * PXB;
    float*       yp = g_Y + (size_t)n * PXB;
    for (int p = tid; p < HWW; p += 256) {
        float v[16];
        #pragma unroll
        for (int s2 = 0; s2 < 16; s2++) v[s2] = vp[s2 * HWW + p];
        #pragma unroll
        for (int t = 0; t < 16; t++) {
            float acc = 0.f;
            #pragma unroll
            for (int s2 = 0; s2 < 16; s2++) acc += A[t * 16 + s2] * v[s2];
            yp[t * HWW + p] = acc;
        }
    }
}

// =====================================================================
// Kernel 4: reconstruction: out = BN(Wr @ Y + br) + x
// grid (49, 4, 8), 256 threads. 8 outs x 8 px per thread. 2 blocks/SM.
// =====================================================================
__global__ __launch_bounds__(256, 2) void recon_kernel(
    const float* __restrict__ x,
    const float* __restrict__ Wr, const float* __restrict__ br,
    const float* __restrict__ gamma, const float* __restrict__ beta,
    const float* __restrict__ bn_mean, const float* __restrict__ bn_var,
    float* __restrict__ out)
{
    const int pxt = blockIdx.x;            // 0..48
    const int oc  = blockIdx.y;            // 0..3
    const int b   = blockIdx.z;
    const int tid = threadIdx.x;
    const int lane = tid & 31;
    const int r    = tid >> 5;
    const int och  = oc * 64;

    __shared__ __align__(16) float Ys[32][256];
    __shared__ __align__(16) unsigned long long Wd[32][64];

    const float* yb = g_Y + (size_t)b * CRr * PXB + pxt * 256;

    unsigned long long acc[8][4];
    #pragma unroll
    for (int o = 0; o < 8; o++)
        #pragma unroll
        for (int h = 0; h < 4; h++) acc[o][h] = 0ULL;

    for (int kt = 0; kt < 128; kt += 32) {
        #pragma unroll 4
        for (int i = 0; i < 8; i++) {
            int idx = tid + i * 256;
            int row = idx >> 6, col = idx & 63;
            float4 v = *(const float4*)(yb + (size_t)(kt + row) * PXB + col * 4);
            *(float4*)(&Ys[row][col * 4]) = v;
        }
        #pragma unroll
        for (int i = 0; i < 2; i++) {
            int idx = tid + i * 256;
            int o = idx >> 3, c4 = idx & 7;
            float4 v = *(const float4*)(Wr + (size_t)(och + o) * CRr + kt + c4 * 4);
            Wd[c4 * 4 + 0][o] = pk2(v.x, v.x);
            Wd[c4 * 4 + 1][o] = pk2(v.y, v.y);
            Wd[c4 * 4 + 2][o] = pk2(v.z, v.z);
            Wd[c4 * 4 + 3][o] = pk2(v.w, v.w);
        }
        __syncthreads();
        #pragma unroll 2
        for (int kk = 0; kk < 32; kk++) {
            ulonglong2 xa = *(const ulonglong2*)(&Ys[kk][lane * 4]);
            ulonglong2 xc = *(const ulonglong2*)(&Ys[kk][128 + lane * 4]);
            const ulonglong2* wp = (const ulonglong2*)(&Wd[kk][r * 8]);
            ulonglong2 w01 = wp[0];
            ulonglong2 w23 = wp[1];
            ulonglong2 w45 = wp[2];
            ulonglong2 w67 = wp[3];
            fma2(acc[0][0], w01.x, xa.x); fma2(acc[0][1], w01.x, xa.y);
            fma2(acc[0][2], w01.x, xc.x); fma2(acc[0][3], w01.x, xc.y);
            fma2(acc[1][0], w01.y, xa.x); fma2(acc[1][1], w01.y, xa.y);
            fma2(acc[1][2], w01.y, xc.x); fma2(acc[1][3], w01.y, xc.y);
            fma2(acc[2][0], w23.x, xa.x); fma2(acc[2][1], w23.x, xa.y);
            fma2(acc[2][2], w23.x, xc.x); fma2(acc[2][3], w23.x, xc.y);
            fma2(acc[3][0], w23.y, xa.x); fma2(acc[3][1], w23.y, xa.y);
            fma2(acc[3][2], w23.y, xc.x); fma2(acc[3][3], w23.y, xc.y);
            fma2(acc[4][0], w45.x, xa.x); fma2(acc[4][1], w45.x, xa.y);
            fma2(acc[4][2], w45.x, xc.x); fma2(acc[4][3], w45.x, xc.y);
            fma2(acc[5][0], w45.y, xa.x); fma2(acc[5][1], w45.y, xa.y);
            fma2(acc[5][2], w45.y, xc.x); fma2(acc[5][3], w45.y, xc.y);
            fma2(acc[6][0], w67.x, xa.x); fma2(acc[6][1], w67.x, xa.y);
            fma2(acc[6][2], w67.x, xc.x); fma2(acc[6][3], w67.x, xc.y);
            fma2(acc[7][0], w67.y, xa.x); fma2(acc[7][1], w67.y, xa.y);
            fma2(acc[7][2], w67.y, xc.x); fma2(acc[7][3], w67.y, xc.y);
        }
        __syncthreads();
    }

    #pragma unroll
    for (int o = 0; o < 8; o++) {
        int ch = och + r * 8 + o;
        float sc = gamma[ch] * rsqrtf(bn_var[ch] + 1e-5f);
        float c0 = sc * br[ch] + beta[ch] - bn_mean[ch] * sc;
        size_t base = (size_t)(b * Cc + ch) * PXB + pxt * 256;
        float4 xv0 = *(const float4*)(x + base + lane * 4);
        float4 xv1 = *(const float4*)(x + base + 128 + lane * 4);
        float y0, y1, y2, y3, y4, y5, y6, y7;
        upk2(acc[o][0], y0, y1); upk2(acc[o][1], y2, y3);
        upk2(acc[o][2], y4, y5); upk2(acc[o][3], y6, y7);
        float4 ov0, ov1;
        ov0.x = sc * y0 + c0 + xv0.x;
        ov0.y = sc * y1 + c0 + xv0.y;
        ov0.z = sc * y2 + c0 + xv0.z;
        ov0.w = sc * y3 + c0 + xv0.w;
        ov1.x = sc * y4 + c0 + xv1.x;
        ov1.y = sc * y5 + c0 + xv1.y;
        ov1.z = sc * y6 + c0 + xv1.z;
        ov1.w = sc * y7 + c0 + xv1.w;
        *(float4*)(out + base + lane * 4)       = ov0;
        *(float4*)(out + base + 128 + lane * 4) = ov1;
    }
}

// =====================================================================
extern "C" void kernel_launch(void* const* d_in, const int* in_sizes, int n_in,
                              void* d_out, int out_size)
{
    const float* x       = (const float*)d_in[0];
    const float* Wq      = (const float*)d_in[1];
    const float* bq      = (const float*)d_in[2];
    const float* Wk      = (const float*)d_in[3];
    const float* bk      = (const float*)d_in[4];
    const float* Wv      = (const float*)d_in[5];
    const float* bv      = (const float*)d_in[6];
    const float* Wr      = (const float*)d_in[7];
    const float* br      = (const float*)d_in[8];
    const float* gamma   = (const float*)d_in[9];
    const float* beta    = (const float*)d_in[10];
    const float* bn_mean = (const float*)d_in[11];
    const float* bn_var  = (const float*)d_in[12];
    float* out = (float*)d_out;

    qkv_kernel<<<dim3(49, 6, Bb), 256>>>(x, Wq, bq, Wk, bk, Wv, bv);
    topk_kernel<<<(2 * NN * Tt) / 8, 256>>>();
    attn_kernel<<<NN, 256>>>();
    recon_kernel<<<dim3(49, 4, Bb), 256>>>(x, Wr, br, gamma, beta,
                                           bn_mean, bn_var, out);
}

// round 11
// speedup vs baseline: 3.1316x; 1.5384x over previous
#include <cuda_runtime.h>
#include <cstdint>

#define Bb   8
#define Cc   256
#define CRr  128
#define Tt   16
#define HWW  784
#define PXB  (Tt * HWW)        // 12544 pixels per (b, channel) slab
#define KTOP 196
#define NN   (Bb * CRr)        // 1024 attention rows

// ---------------- scratch (device globals; no allocation allowed) ----------------
__device__ float g_Q[NN * PXB];        // [n][t][hw]
__device__ float g_K[NN * PXB];
__device__ float g_V[NN * PXB];
__device__ float g_Qtk[NN * Tt * KTOP];
__device__ float g_Ktk[NN * Tt * KTOP];
__device__ float g_Y[NN * PXB];

// ---------------- bf16 helpers ----------------
__device__ __forceinline__ unsigned short bf16h(float v) {
    unsigned short h;
    asm("cvt.rn.bf16.f32 %0, %1;" : "=h"(h) : "f"(v));
    return h;
}
__device__ __forceinline__ float bf16f(unsigned short h) {
    return __uint_as_float(((uint32_t)h) << 16);
}

// mma.sync m16n8k16 row.col bf16 -> f32 accumulate (sm_80+ baseline PTX)
#define MMA_BF16(cf, a, b) \
    asm volatile("mma.sync.aligned.m16n8k16.row.col.f32.bf16.bf16.f32 " \
        "{%0,%1,%2,%3}, {%4,%5,%6,%7}, {%8,%9}, {%0,%1,%2,%3};" \
        : "+f"((cf)[0]), "+f"((cf)[1]), "+f"((cf)[2]), "+f"((cf)[3]) \
        : "r"((a)[0]), "r"((a)[1]), "r"((a)[2]), "r"((a)[3]), \
          "r"((b)[0]), "r"((b)[1]))

// smem tile geometry: rows of 64 bf16 payload, padded to 72 bf16 (36 b32 words)
// -> fragment LDS bank = (4*g + t) all-distinct, conflict-free.
#define TSTR 36                 // b32 words per row
#define TILE_B32 (128 * TSTR)   // 4608 words = 18432 B per tile
#define SM_AH 0
#define SM_AL (SM_AH + 18432)
#define SM_BH (SM_AL + 18432)
#define SM_BL (SM_BH + 18432)
#define SM_E0 (SM_BL + 18432)   // 128 floats (bias | sc)
#define SM_E1 (SM_E0 + 512)     // 128 floats (c0, recon only)
#define SM_TOT (SM_E1 + 512)    // 74752 B dynamic smem

// =====================================================================
// Kernel 1: QKV via bf16-split HMMA.  D[128 px][128 outs] per block.
// grid (98 px-tiles, 3 out-chunks = Q/K/V, 8 batches), 256 threads.
// Split: D = Ahi*Bhi + Ahi*Blo + Alo*Bhi   (bf16 in, fp32 accum)
// =====================================================================
__global__ __launch_bounds__(256, 2) void qkv_mma_kernel(
    const float* __restrict__ x,
    const float* __restrict__ Wq, const float* __restrict__ bq,
    const float* __restrict__ Wk, const float* __restrict__ bk,
    const float* __restrict__ Wv, const float* __restrict__ bv)
{
    extern __shared__ __align__(16) char smem[];
    uint32_t* A32h = (uint32_t*)(smem + SM_AH);
    uint32_t* A32l = (uint32_t*)(smem + SM_AL);
    uint32_t* B32h = (uint32_t*)(smem + SM_BH);
    uint32_t* B32l = (uint32_t*)(smem + SM_BL);
    float*    biasS = (float*)(smem + SM_E0);

    const int pxt = blockIdx.x;            // 0..97
    const int oc  = blockIdx.y;            // 0:Q 1:K 2:V
    const int b   = blockIdx.z;
    const int tid = threadIdx.x;
    const int wid = tid >> 5;
    const int lane = tid & 31;
    const int g = lane >> 2, t = lane & 3;
    const int wm = wid >> 1, wn = wid & 1;  // warp tile: 32 px x 64 outs

    const float* W    = (oc == 0) ? Wq : (oc == 1) ? Wk : Wv;
    const float* bias = (oc == 0) ? bq : (oc == 1) ? bk : bv;
    float*       dst  = (oc == 0) ? g_Q : (oc == 1) ? g_K : g_V;

    if (tid < 128) biasS[tid] = bias[tid];

    float c[2][8][4];
    #pragma unroll
    for (int i = 0; i < 2; i++)
        #pragma unroll
        for (int j = 0; j < 8; j++)
            #pragma unroll
            for (int r = 0; r < 4; r++) c[i][j][r] = 0.f;

    const int arow0 = (wm * 32 + g) * TSTR;
    const int brow0 = (wn * 64 + g) * TSTR;

    for (int kt = 0; kt < 4; kt++) {       // K chunks of 64
        // ---- A fill: x transposed to [px][k], 4096 b32 elems
        #pragma unroll 4
        for (int i = 0; i < 16; i++) {
            int e = tid + i * 256;
            int px = e & 127, kp = e >> 7;
            const float* xp = x + ((size_t)(b * Cc + kt * 64 + kp * 2)) * PXB
                                + (size_t)pxt * 128 + px;
            float v0 = xp[0], v1 = xp[PXB];
            unsigned short h0 = bf16h(v0), h1 = bf16h(v1);
            unsigned short l0 = bf16h(v0 - bf16f(h0));
            unsigned short l1 = bf16h(v1 - bf16f(h1));
            A32h[px * TSTR + kp] = ((uint32_t)h1 << 16) | h0;
            A32l[px * TSTR + kp] = ((uint32_t)l1 << 16) | l0;
        }
        // ---- B fill: W[n][k], 4096 b32 elems
        #pragma unroll 4
        for (int i = 0; i < 16; i++) {
            int e = tid + i * 256;
            int n = e >> 5, kp = e & 31;
            float2 wv = *(const float2*)(W + (size_t)n * Cc + kt * 64 + kp * 2);
            unsigned short h0 = bf16h(wv.x), h1 = bf16h(wv.y);
            unsigned short l0 = bf16h(wv.x - bf16f(h0));
            unsigned short l1 = bf16h(wv.y - bf16f(h1));
            B32h[n * TSTR + kp] = ((uint32_t)h1 << 16) | h0;
            B32l[n * TSTR + kp] = ((uint32_t)l1 << 16) | l0;
        }
        __syncthreads();

        #pragma unroll
        for (int kq = 0; kq < 4; kq++) {   // k16 steps within chunk
            const int co = kq * 8 + t;
            uint32_t ah[2][4], al[2][4], bb[8][2];
            #pragma unroll
            for (int i = 0; i < 2; i++) {
                int base = arow0 + i * (16 * TSTR) + co;
                ah[i][0] = A32h[base];
                ah[i][1] = A32h[base + 8 * TSTR];
                ah[i][2] = A32h[base + 4];
                ah[i][3] = A32h[base + 8 * TSTR + 4];
                al[i][0] = A32l[base];
                al[i][1] = A32l[base + 8 * TSTR];
                al[i][2] = A32l[base + 4];
                al[i][3] = A32l[base + 8 * TSTR + 4];
            }
            #pragma unroll
            for (int j = 0; j < 8; j++) {
                int base = brow0 + j * (8 * TSTR) + co;
                bb[j][0] = B32h[base];
                bb[j][1] = B32h[base + 4];
            }
            #pragma unroll
            for (int i = 0; i < 2; i++)
                #pragma unroll
                for (int j = 0; j < 8; j++) {
                    MMA_BF16(c[i][j], ah[i], bb[j]);   // hi*hi
                    MMA_BF16(c[i][j], al[i], bb[j]);   // lo*hi
                }
            #pragma unroll
            for (int j = 0; j < 8; j++) {
                int base = brow0 + j * (8 * TSTR) + co;
                bb[j][0] = B32l[base];
                bb[j][1] = B32l[base + 4];
            }
            #pragma unroll
            for (int i = 0; i < 2; i++)
                #pragma unroll
                for (int j = 0; j < 8; j++)
                    MMA_BF16(c[i][j], ah[i], bb[j]);   // hi*lo
        }
        __syncthreads();
    }

    // ---- epilogue: + bias, scatter to dst[ch][px]
    #pragma unroll
    for (int i = 0; i < 2; i++) {
        #pragma unroll
        for (int j = 0; j < 8; j++) {
            #pragma unroll
            for (int r = 0; r < 4; r++) {
                int px = pxt * 128 + wm * 32 + i * 16 + g + ((r >> 1) * 8);
                int ch = wn * 64 + j * 8 + t * 2 + (r & 1);
                dst[((size_t)(b * CRr + ch)) * PXB + px] = c[i][j][r] + biasS[ch];
            }
        }
    }
}

// =====================================================================
// Kernel 2: top-196 sorted descending per (n,t) row — warp-register bitonic.
// =====================================================================
#define NEG_INF __int_as_float(0xff800000)

template<int RJ, int KR>
__device__ __forceinline__ void bt_intra(float* v) {
    #pragma unroll
    for (int rr = 0; rr < 32; rr++) {
        if ((rr & RJ) == 0) {
            const int r2 = rr | RJ;
            const bool up = ((rr & KR) == 0);
            float a = v[rr], bvv = v[r2];
            v[rr] = up ? fmaxf(a, bvv) : fminf(a, bvv);
            v[r2] = up ? fminf(a, bvv) : fmaxf(a, bvv);
        }
    }
}

template<int KR>
__device__ __forceinline__ void bt_shfl(float* v, unsigned lane) {
    for (int j = 16; j >= 1; j >>= 1) {
        const bool lower = ((lane & j) == 0);
        #pragma unroll
        for (int rr = 0; rr < 32; rr++) {
            float bvv = __shfl_xor_sync(0xffffffffu, v[rr], j);
            const bool up = ((rr & KR) == 0);
            const bool keep_max = (up == lower);
            v[rr] = keep_max ? fmaxf(v[rr], bvv) : fminf(v[rr], bvv);
        }
    }
}

__global__ __launch_bounds__(256) void topk_kernel()
{
    const unsigned lane = threadIdx.x & 31;
    const int wid = threadIdx.x >> 5;
    const int row = blockIdx.x * 8 + wid;
    const int rl  = row & 16383;
    const float* src; float* dst;
    if (row < 16384) { src = g_Q; dst = g_Qtk; }
    else             { src = g_K; dst = g_Ktk; }
    const float* p = src + (size_t)rl * HWW;

    float v[32];
    #pragma unroll
    for (int rr = 0; rr < 32; rr++) {
        int idx = rr * 32 + (int)lane;
        v[rr] = (idx < HWW) ? p[idx] : NEG_INF;
    }

    for (int k = 2; k <= 16; k <<= 1) {
        for (int j = k >> 1; j >= 1; j >>= 1) {
            const bool eq = (((lane & k) == 0) == ((lane & j) == 0));
            #pragma unroll
            for (int rr = 0; rr < 32; rr++) {
                float bvv = __shfl_xor_sync(0xffffffffu, v[rr], j);
                v[rr] = eq ? fmaxf(v[rr], bvv) : fminf(v[rr], bvv);
            }
        }
    }
    bt_shfl<1>(v, lane);
    bt_intra<1, 2>(v);  bt_shfl<2>(v, lane);
    bt_intra<2, 4>(v);  bt_intra<1, 4>(v);  bt_shfl<4>(v, lane);
    bt_intra<4, 8>(v);  bt_intra<2, 8>(v);  bt_intra<1, 8>(v);  bt_shfl<8>(v, lane);
    bt_intra<8, 16>(v); bt_intra<4, 16>(v); bt_intra<2, 16>(v); bt_intra<1, 16>(v);
    bt_shfl<16>(v, lane);
    bt_intra<16, 32>(v); bt_intra<8, 32>(v); bt_intra<4, 32>(v); bt_intra<2, 32>(v);
    bt_intra<1, 32>(v);  bt_shfl<32>(v, lane);

    float* q = dst + (size_t)rl * KTOP;
    #pragma unroll
    for (int rr = 0; rr < 6; rr++)
        q[rr * 32 + lane] = v[rr];
    if (lane < 4) q[192 + lane] = v[6];
}

// =====================================================================
// Kernel 3: per-n attention: corr = Qtk@Ktk^T (16x16), softmax, Y = attn@V
// =====================================================================
__global__ __launch_bounds__(256) void attn_kernel()
{
    __shared__ float Qs[Tt * KTOP];
    __shared__ float Ks[Tt * KTOP];
    __shared__ float A[Tt * Tt];
    const int n   = blockIdx.x;
    const int tid = threadIdx.x;

    const float* qp = g_Qtk + (size_t)n * Tt * KTOP;
    const float* kp = g_Ktk + (size_t)n * Tt * KTOP;
    for (int i = tid; i < Tt * KTOP; i += 256) { Qs[i] = qp[i]; Ks[i] = kp[i]; }
    __syncthreads();

    {
        const int t = tid >> 4, s2 = tid & 15;
        float acc = 0.f;
        #pragma unroll 4
        for (int k = 0; k < KTOP; k++)
            acc += Qs[t * KTOP + k] * Ks[s2 * KTOP + k];
        A[t * 16 + s2] = acc;
    }
    __syncthreads();

    if (tid < 16) {
        float m = -1e30f;
        #pragma unroll
        for (int s2 = 0; s2 < 16; s2++) m = fmaxf(m, A[tid * 16 + s2]);
        float e[16], sum = 0.f;
        #pragma unroll
        for (int s2 = 0; s2 < 16; s2++) {
            e[s2] = __expf(A[tid * 16 + s2] - m);
            sum += e[s2];
        }
        float inv = 1.0f / sum;
        #pragma unroll
        for (int s2 = 0; s2 < 16; s2++) A[tid * 16 + s2] = e[s2] * inv;
    }
    __syncthreads();

    const float* vp = g_V + (size_t)n * PXB;
    float*       yp = g_Y + (size_t)n * PXB;
    for (int p = tid; p < HWW; p += 256) {
        float v[16];
        #pragma unroll
        for (int s2 = 0; s2 < 16; s2++) v[s2] = vp[s2 * HWW + p];
        #pragma unroll
        for (int t = 0; t < 16; t++) {
            float acc = 0.f;
            #pragma unroll
            for (int s2 = 0; s2 < 16; s2++) acc += A[t * 16 + s2] * v[s2];
            yp[t * HWW + p] = acc;
        }
    }
}

// =====================================================================
// Kernel 4: recon via bf16-split HMMA: out = BN(Wr @ Y + br) + x
// grid (98 px-tiles, 2 out-chunks of 128, 8 batches), 256 threads.
// =====================================================================
__global__ __launch_bounds__(256, 2) void recon_mma_kernel(
    const float* __restrict__ x,
    const float* __restrict__ Wr, const float* __restrict__ br,
    const float* __restrict__ gamma, const float* __restrict__ beta,
    const float* __restrict__ bn_mean, const float* __restrict__ bn_var,
    float* __restrict__ out)
{
    extern __shared__ __align__(16) char smem[];
    uint32_t* A32h = (uint32_t*)(smem + SM_AH);
    uint32_t* A32l = (uint32_t*)(smem + SM_AL);
    uint32_t* B32h = (uint32_t*)(smem + SM_BH);
    uint32_t* B32l = (uint32_t*)(smem + SM_BL);
    float*    scS  = (float*)(smem + SM_E0);
    float*    c0S  = (float*)(smem + SM_E1);

    const int pxt = blockIdx.x;
    const int oc  = blockIdx.y;            // 0..1 (128 outs each)
    const int b   = blockIdx.z;
    const int tid = threadIdx.x;
    const int wid = tid >> 5;
    const int lane = tid & 31;
    const int g = lane >> 2, t = lane & 3;
    const int wm = wid >> 1, wn = wid & 1;

    if (tid < 128) {
        int ch = oc * 128 + tid;
        float sc = gamma[ch] * rsqrtf(bn_var[ch] + 1e-5f);
        scS[tid] = sc;
        c0S[tid] = sc * br[ch] + beta[ch] - bn_mean[ch] * sc;
    }

    float c[2][8][4];
    #pragma unroll
    for (int i = 0; i < 2; i++)
        #pragma unroll
        for (int j = 0; j < 8; j++)
            #pragma unroll
            for (int r = 0; r < 4; r++) c[i][j][r] = 0.f;

    const int arow0 = (wm * 32 + g) * TSTR;
    const int brow0 = (wn * 64 + g) * TSTR;

    for (int kt = 0; kt < 2; kt++) {       // K = 128: 2 chunks of 64
        #pragma unroll 4
        for (int i = 0; i < 16; i++) {
            int e = tid + i * 256;
            int px = e & 127, kp = e >> 7;
            const float* yp = g_Y + ((size_t)(b * CRr + kt * 64 + kp * 2)) * PXB
                                  + (size_t)pxt * 128 + px;
            float v0 = yp[0], v1 = yp[PXB];
            unsigned short h0 = bf16h(v0), h1 = bf16h(v1);
            unsigned short l0 = bf16h(v0 - bf16f(h0));
            unsigned short l1 = bf16h(v1 - bf16f(h1));
            A32h[px * TSTR + kp] = ((uint32_t)h1 << 16) | h0;
            A32l[px * TSTR + kp] = ((uint32_t)l1 << 16) | l0;
        }
        #pragma unroll 4
        for (int i = 0; i < 16; i++) {
            int e = tid + i * 256;
            int n = e >> 5, kp = e & 31;
            float2 wv = *(const float2*)(Wr + (size_t)(oc * 128 + n) * CRr
                                            + kt * 64 + kp * 2);
            unsigned short h0 = bf16h(wv.x), h1 = bf16h(wv.y);
            unsigned short l0 = bf16h(wv.x - bf16f(h0));
            unsigned short l1 = bf16h(wv.y - bf16f(h1));
            B32h[n * TSTR + kp] = ((uint32_t)h1 << 16) | h0;
            B32l[n * TSTR + kp] = ((uint32_t)l1 << 16) | l0;
        }
        __syncthreads();

        #pragma unroll
        for (int kq = 0; kq < 4; kq++) {
            const int co = kq * 8 + t;
            uint32_t ah[2][4], al[2][4], bb[8][2];
            #pragma unroll
            for (int i = 0; i < 2; i++) {
                int base = arow0 + i * (16 * TSTR) + co;
                ah[i][0] = A32h[base];
                ah[i][1] = A32h[base + 8 * TSTR];
                ah[i][2] = A32h[base + 4];
                ah[i][3] = A32h[base + 8 * TSTR + 4];
                al[i][0] = A32l[base];
                al[i][1] = A32l[base + 8 * TSTR];
                al[i][2] = A32l[base + 4];
                al[i][3] = A32l[base + 8 * TSTR + 4];
            }
            #pragma unroll
            for (int j = 0; j < 8; j++) {
                int base = brow0 + j * (8 * TSTR) + co;
                bb[j][0] = B32h[base];
                bb[j][1] = B32h[base + 4];
            }
            #pragma unroll
            for (int i = 0; i < 2; i++)
                #pragma unroll
                for (int j = 0; j < 8; j++) {
                    MMA_BF16(c[i][j], ah[i], bb[j]);
                    MMA_BF16(c[i][j], al[i], bb[j]);
                }
            #pragma unroll
            for (int j = 0; j < 8; j++) {
                int base = brow0 + j * (8 * TSTR) + co;
                bb[j][0] = B32l[base];
                bb[j][1] = B32l[base + 4];
            }
            #pragma unroll
            for (int i = 0; i < 2; i++)
                #pragma unroll
                for (int j = 0; j < 8; j++)
                    MMA_BF16(c[i][j], ah[i], bb[j]);
        }
        __syncthreads();
    }

    // ---- epilogue: BN + residual
    #pragma unroll
    for (int i = 0; i < 2; i++) {
        #pragma unroll
        for (int j = 0; j < 8; j++) {
            #pragma unroll
            for (int r = 0; r < 4; r++) {
                int px  = pxt * 128 + wm * 32 + i * 16 + g + ((r >> 1) * 8);
                int chl = wn * 64 + j * 8 + t * 2 + (r & 1);
                int chg = oc * 128 + chl;
                size_t addr = ((size_t)(b * Cc + chg)) * PXB + px;
                out[addr] = scS[chl] * c[i][j][r] + c0S[chl] + x[addr];
            }
        }
    }
}

// =====================================================================
extern "C" void kernel_launch(void* const* d_in, const int* in_sizes, int n_in,
                              void* d_out, int out_size)
{
    const float* x       = (const float*)d_in[0];
    const float* Wq      = (const float*)d_in[1];
    const float* bq      = (const float*)d_in[2];
    const float* Wk      = (const float*)d_in[3];
    const float* bk      = (const float*)d_in[4];
    const float* Wv      = (const float*)d_in[5];
    const float* bv      = (const float*)d_in[6];
    const float* Wr      = (const float*)d_in[7];
    const float* br      = (const float*)d_in[8];
    const float* gamma   = (const float*)d_in[9];
    const float* beta    = (const float*)d_in[10];
    const float* bn_mean = (const float*)d_in[11];
    const float* bn_var  = (const float*)d_in[12];
    float* out = (float*)d_out;

    cudaFuncSetAttribute(qkv_mma_kernel,
                         cudaFuncAttributeMaxDynamicSharedMemorySize, SM_TOT);
    cudaFuncSetAttribute(recon_mma_kernel,
                         cudaFuncAttributeMaxDynamicSharedMemorySize, SM_TOT);

    qkv_mma_kernel<<<dim3(98, 3, Bb), 256, SM_TOT>>>(x, Wq, bq, Wk, bk, Wv, bv);
    topk_kernel<<<(2 * NN * Tt) / 8, 256>>>();
    attn_kernel<<<NN, 256>>>();
    recon_mma_kernel<<<dim3(98, 2, Bb), 256, SM_TOT>>>(x, Wr, br, gamma, beta,
                                                       bn_mean, bn_var, out);
}